// round 2
// baseline (speedup 1.0000x reference)
#include <cuda_runtime.h>
#include <math.h>

// Problem constants
#define BB 4
#define SEQ 2048
#define DMODEL 1024
#define NHEAD 16
#define DHEAD 64
#define MROWS (BB * SEQ)   // 8192

// Scratch (static device globals — allocation is forbidden)
__device__ float g_Qh[BB * NHEAD * SEQ * DHEAD];   // [B,H,S,d]
__device__ float g_Kh[BB * NHEAD * SEQ * DHEAD];
__device__ float g_Vh[BB * NHEAD * SEQ * DHEAD];
__device__ float g_Ctx[MROWS * DMODEL];            // [B,S,D] head-concat

// ---------------------------------------------------------------------------
// SGEMM: X[M x 1024] @ W[1024 x 1024] + bias, 128x128x8 tiles, 8x8 microtile.
// Projection variant writes into [B,H,S,d] layout. grid.z selects q/k/v.
// ---------------------------------------------------------------------------
__global__ __launch_bounds__(256) void proj_kernel(
    const float* __restrict__ q, const float* __restrict__ k,
    const float* __restrict__ v,
    const float* __restrict__ Wq, const float* __restrict__ bq,
    const float* __restrict__ Wk, const float* __restrict__ bk,
    const float* __restrict__ Wv, const float* __restrict__ bv)
{
    const float* X; const float* W; const float* bias; float* out;
    if (blockIdx.z == 0)      { X = q; W = Wq; bias = bq; out = g_Qh; }
    else if (blockIdx.z == 1) { X = k; W = Wk; bias = bk; out = g_Kh; }
    else                      { X = v; W = Wv; bias = bv; out = g_Vh; }

    __shared__ float As[8][128];
    __shared__ float Bs[8][128];

    const int tid = threadIdx.x;
    const int m0 = blockIdx.y * 128;
    const int n0 = blockIdx.x * 128;
    const int arow = tid >> 1, acol = (tid & 1) * 4;
    const int brow = tid >> 5, bcol = (tid & 31) * 4;
    const int ty = tid >> 4, tx = tid & 15;

    float acc[8][8];
#pragma unroll
    for (int i = 0; i < 8; i++)
#pragma unroll
        for (int j = 0; j < 8; j++) acc[i][j] = 0.f;

    for (int kt = 0; kt < DMODEL; kt += 8) {
        float4 av = *(const float4*)&X[(size_t)(m0 + arow) * DMODEL + kt + acol];
        As[acol + 0][arow] = av.x;
        As[acol + 1][arow] = av.y;
        As[acol + 2][arow] = av.z;
        As[acol + 3][arow] = av.w;
        float4 bv4 = *(const float4*)&W[(size_t)(kt + brow) * DMODEL + n0 + bcol];
        *(float4*)&Bs[brow][bcol] = bv4;
        __syncthreads();

#pragma unroll
        for (int kk = 0; kk < 8; kk++) {
            float4 ra0 = *(const float4*)&As[kk][ty * 8];
            float4 ra1 = *(const float4*)&As[kk][ty * 8 + 4];
            float4 rb0 = *(const float4*)&Bs[kk][tx * 8];
            float4 rb1 = *(const float4*)&Bs[kk][tx * 8 + 4];
            float ra[8] = {ra0.x, ra0.y, ra0.z, ra0.w, ra1.x, ra1.y, ra1.z, ra1.w};
            float rb[8] = {rb0.x, rb0.y, rb0.z, rb0.w, rb1.x, rb1.y, rb1.z, rb1.w};
#pragma unroll
            for (int i = 0; i < 8; i++)
#pragma unroll
                for (int j = 0; j < 8; j++)
                    acc[i][j] = fmaf(ra[i], rb[j], acc[i][j]);
        }
        __syncthreads();
    }

#pragma unroll
    for (int i = 0; i < 8; i++) {
        int m = m0 + ty * 8 + i;
        int b = m >> 11;          // m / SEQ
        int s = m & (SEQ - 1);
#pragma unroll
        for (int j = 0; j < 8; j++) {
            int n = n0 + tx * 8 + j;
            int h = n >> 6;       // n / DHEAD
            int dd = n & 63;
            float val = acc[i][j] + bias[n];
            out[(((size_t)(b * NHEAD + h) * SEQ) + s) * DHEAD + dd] = val;
        }
    }
}

// ---------------------------------------------------------------------------
// Output projection: g_Ctx[8192 x 1024] @ Wo + bo -> out (plain [B,S,D])
// ---------------------------------------------------------------------------
__global__ __launch_bounds__(256) void outproj_kernel(
    const float* __restrict__ Wo, const float* __restrict__ bo,
    float* __restrict__ out)
{
    __shared__ float As[8][128];
    __shared__ float Bs[8][128];

    const int tid = threadIdx.x;
    const int m0 = blockIdx.y * 128;
    const int n0 = blockIdx.x * 128;
    const int arow = tid >> 1, acol = (tid & 1) * 4;
    const int brow = tid >> 5, bcol = (tid & 31) * 4;
    const int ty = tid >> 4, tx = tid & 15;

    float acc[8][8];
#pragma unroll
    for (int i = 0; i < 8; i++)
#pragma unroll
        for (int j = 0; j < 8; j++) acc[i][j] = 0.f;

    for (int kt = 0; kt < DMODEL; kt += 8) {
        float4 av = *(const float4*)&g_Ctx[(size_t)(m0 + arow) * DMODEL + kt + acol];
        As[acol + 0][arow] = av.x;
        As[acol + 1][arow] = av.y;
        As[acol + 2][arow] = av.z;
        As[acol + 3][arow] = av.w;
        float4 bv4 = *(const float4*)&Wo[(size_t)(kt + brow) * DMODEL + n0 + bcol];
        *(float4*)&Bs[brow][bcol] = bv4;
        __syncthreads();

#pragma unroll
        for (int kk = 0; kk < 8; kk++) {
            float4 ra0 = *(const float4*)&As[kk][ty * 8];
            float4 ra1 = *(const float4*)&As[kk][ty * 8 + 4];
            float4 rb0 = *(const float4*)&Bs[kk][tx * 8];
            float4 rb1 = *(const float4*)&Bs[kk][tx * 8 + 4];
            float ra[8] = {ra0.x, ra0.y, ra0.z, ra0.w, ra1.x, ra1.y, ra1.z, ra1.w};
            float rb[8] = {rb0.x, rb0.y, rb0.z, rb0.w, rb1.x, rb1.y, rb1.z, rb1.w};
#pragma unroll
            for (int i = 0; i < 8; i++)
#pragma unroll
                for (int j = 0; j < 8; j++)
                    acc[i][j] = fmaf(ra[i], rb[j], acc[i][j]);
        }
        __syncthreads();
    }

#pragma unroll
    for (int i = 0; i < 8; i++) {
        int m = m0 + ty * 8 + i;
#pragma unroll
        for (int j = 0; j < 8; j++) {
            int n = n0 + tx * 8 + j;
            out[(size_t)m * DMODEL + n] = acc[i][j] + bo[n];
        }
    }
}

// ---------------------------------------------------------------------------
// Flash attention: per (b,h, 64-row q-tile). Online softmax over 32-key tiles.
// Thread layout 16x16: each thread owns 4 q-rows, 2 k-cols (S) and 4 d-cols (O).
// Static shared memory = 41,728 bytes (< 48 KB, no attribute call needed).
// ---------------------------------------------------------------------------
#define QPAD 65
#define PPAD 33
__global__ __launch_bounds__(256) void attn_kernel(const int* __restrict__ mask)
{
    __shared__ float Qs[64 * QPAD];
    __shared__ float Ks[32 * QPAD];
    __shared__ float Vs[32 * QPAD];
    __shared__ float Ps[64 * PPAD];

    const int bh = blockIdx.y;          // b*16 + h
    const int b = bh >> 4;
    const int h = bh & 15;
    const int qt = blockIdx.x;          // q tile (64 rows)
    const int tid = threadIdx.x;
    const int ty = tid >> 4, tx = tid & 15;

    const float* Qbase = g_Qh + ((size_t)bh * SEQ + qt * 64) * DHEAD;
    const float* Kbase = g_Kh + (size_t)bh * SEQ * DHEAD;
    const float* Vbase = g_Vh + (size_t)bh * SEQ * DHEAD;
    const int* mrow = mask + b * SEQ;

    // load Q tile (64 x 64)
    for (int i = tid; i < 64 * 64; i += 256) {
        int r = i >> 6, c = i & 63;
        Qs[r * QPAD + c] = Qbase[i];
    }

    float m_i[4], l_i[4], O[4][4];
#pragma unroll
    for (int i = 0; i < 4; i++) {
        m_i[i] = -1e30f; l_i[i] = 0.f;
#pragma unroll
        for (int j = 0; j < 4; j++) O[i][j] = 0.f;
    }
    __syncthreads();

    for (int kt = 0; kt < SEQ; kt += 32) {
        // stage K,V tiles (32 x 64): 2048 elems each, 8 per thread
        for (int i = tid; i < 32 * 64; i += 256) {
            int r = i >> 6, c = i & 63;
            Ks[r * QPAD + c] = Kbase[(size_t)(kt + r) * DHEAD + c];
            Vs[r * QPAD + c] = Vbase[(size_t)(kt + r) * DHEAD + c];
        }
        __syncthreads();

        // S = Q K^T : per-thread 4x2
        float s[4][2];
#pragma unroll
        for (int i = 0; i < 4; i++) { s[i][0] = 0.f; s[i][1] = 0.f; }

#pragma unroll 8
        for (int kk = 0; kk < 64; kk++) {
            float ra[4], rb[2];
#pragma unroll
            for (int i = 0; i < 4; i++) ra[i] = Qs[(ty * 4 + i) * QPAD + kk];
            rb[0] = Ks[(tx * 2 + 0) * QPAD + kk];
            rb[1] = Ks[(tx * 2 + 1) * QPAD + kk];
#pragma unroll
            for (int i = 0; i < 4; i++) {
                s[i][0] = fmaf(ra[i], rb[0], s[i][0]);
                s[i][1] = fmaf(ra[i], rb[1], s[i][1]);
            }
        }

        // scale + mask (mask is 0/1, times LARGE_NEG)
        float cb0 = (float)mrow[kt + tx * 2 + 0] * (-1000000000.0f);
        float cb1 = (float)mrow[kt + tx * 2 + 1] * (-1000000000.0f);
#pragma unroll
        for (int i = 0; i < 4; i++) {
            s[i][0] = s[i][0] * 0.125f + cb0;
            s[i][1] = s[i][1] * 0.125f + cb1;
        }

        // row max across the 16 tx threads (xor shuffle stays in half-warp)
        float mnew[4];
#pragma unroll
        for (int i = 0; i < 4; i++) {
            float t = fmaxf(s[i][0], s[i][1]);
#pragma unroll
            for (int o = 8; o >= 1; o >>= 1)
                t = fmaxf(t, __shfl_xor_sync(0xffffffffu, t, o));
            mnew[i] = fmaxf(m_i[i], t);
        }

        // p = exp(s - mnew); row sums; rescale accumulators
        float rowsum[4];
#pragma unroll
        for (int i = 0; i < 4; i++) {
            s[i][0] = __expf(s[i][0] - mnew[i]);
            s[i][1] = __expf(s[i][1] - mnew[i]);
            float rs = s[i][0] + s[i][1];
#pragma unroll
            for (int o = 8; o >= 1; o >>= 1)
                rs += __shfl_xor_sync(0xffffffffu, rs, o);
            rowsum[i] = rs;
        }
#pragma unroll
        for (int i = 0; i < 4; i++) {
            float alpha = __expf(m_i[i] - mnew[i]);
            l_i[i] = l_i[i] * alpha + rowsum[i];
            m_i[i] = mnew[i];
#pragma unroll
            for (int j = 0; j < 4; j++) O[i][j] *= alpha;
        }

        // publish P (64 x 32)
#pragma unroll
        for (int i = 0; i < 4; i++) {
            Ps[(ty * 4 + i) * PPAD + tx * 2 + 0] = s[i][0];
            Ps[(ty * 4 + i) * PPAD + tx * 2 + 1] = s[i][1];
        }
        __syncthreads();

        // O += P(64x32) V(32x64): per-thread 4 rows x 4 d-cols
#pragma unroll 8
        for (int j = 0; j < 32; j++) {
            float pr[4], vr[4];
#pragma unroll
            for (int i = 0; i < 4; i++) pr[i] = Ps[(ty * 4 + i) * PPAD + j];
#pragma unroll
            for (int jj = 0; jj < 4; jj++) vr[jj] = Vs[j * QPAD + tx * 4 + jj];
#pragma unroll
            for (int i = 0; i < 4; i++)
#pragma unroll
                for (int jj = 0; jj < 4; jj++)
                    O[i][jj] = fmaf(pr[i], vr[jj], O[i][jj]);
        }
        __syncthreads();
    }

    // write ctx in head-concat layout [B,S,D]
#pragma unroll
    for (int i = 0; i < 4; i++) {
        int row = qt * 64 + ty * 4 + i;
        float inv = 1.0f / l_i[i];
#pragma unroll
        for (int j = 0; j < 4; j++) {
            int col = h * DHEAD + tx * 4 + j;
            g_Ctx[((size_t)b * SEQ + row) * DMODEL + col] = O[i][j] * inv;
        }
    }
}

// ---------------------------------------------------------------------------
// Launch: pure kernel launches, nothing else (graph-capture safe).
// ---------------------------------------------------------------------------
extern "C" void kernel_launch(void* const* d_in, const int* in_sizes, int n_in,
                              void* d_out, int out_size)
{
    const float* v  = (const float*)d_in[0];
    const float* k  = (const float*)d_in[1];
    const float* q  = (const float*)d_in[2];
    const int*   mask = (const int*)d_in[3];
    const float* Wq = (const float*)d_in[4];
    const float* bq = (const float*)d_in[5];
    const float* Wk = (const float*)d_in[6];
    const float* bk = (const float*)d_in[7];
    const float* Wv = (const float*)d_in[8];
    const float* bv = (const float*)d_in[9];
    const float* Wo = (const float*)d_in[10];
    const float* bo = (const float*)d_in[11];
    float* out = (float*)d_out;

    // QKV projections (grid.z selects which)
    dim3 gproj(DMODEL / 128, MROWS / 128, 3);
    proj_kernel<<<gproj, 256>>>(q, k, v, Wq, bq, Wk, bk, Wv, bv);

    // Flash attention (static smem only)
    dim3 gattn(SEQ / 64, BB * NHEAD);
    attn_kernel<<<gattn, 256>>>(mask);

    // Output projection
    dim3 gout(DMODEL / 128, MROWS / 128);
    outproj_kernel<<<gout, 256>>>(Wo, bo, out);
}

// round 6
// speedup vs baseline: 1.3639x; 1.3639x over previous
#include <cuda_runtime.h>
#include <cuda_bf16.h>
#include <cstdint>
#include <math.h>

// Problem constants
#define BB 4
#define SEQ 2048
#define DMODEL 1024
#define NHEAD 16
#define DHEAD 64
#define MROWS (BB * SEQ)   // 8192

// ---------------------------------------------------------------------------
// Device-global scratch (allocation is forbidden)
// ---------------------------------------------------------------------------
__device__ float g_Qh[BB * NHEAD * SEQ * DHEAD];   // [B,H,S,d]
__device__ float g_Kh[BB * NHEAD * SEQ * DHEAD];
__device__ float g_Vh[BB * NHEAD * SEQ * DHEAD];

// bf16 split operands
__device__ __nv_bfloat16 g_Xhi[3 * MROWS * DMODEL];   // q,k,v rows [M,K]
__device__ __nv_bfloat16 g_Xlo[3 * MROWS * DMODEL];
__device__ __nv_bfloat16 g_Wthi[4 * DMODEL * DMODEL]; // W transposed [N,K]
__device__ __nv_bfloat16 g_Wtlo[4 * DMODEL * DMODEL];
__device__ __nv_bfloat16 g_Chi[MROWS * DMODEL];       // attention ctx hi/lo
__device__ __nv_bfloat16 g_Clo[MROWS * DMODEL];

// ---------------------------------------------------------------------------
// mma.sync / ldmatrix helpers (baseline PTX, works on plain sm_103 target)
// ---------------------------------------------------------------------------
__device__ __forceinline__ uint32_t smem_u32(const void* p) {
    uint32_t a;
    asm("{ .reg .u64 t; cvta.to.shared.u64 t, %1; cvt.u32.u64 %0, t; }"
        : "=r"(a) : "l"(p));
    return a;
}
__device__ __forceinline__ void ldsm4(uint32_t* r, uint32_t addr) {
    asm volatile("ldmatrix.sync.aligned.m8n8.x4.shared.b16 {%0,%1,%2,%3}, [%4];"
                 : "=r"(r[0]), "=r"(r[1]), "=r"(r[2]), "=r"(r[3]) : "r"(addr));
}
__device__ __forceinline__ void mma16816(float* d, const uint32_t* a, const uint32_t* b) {
    asm volatile("mma.sync.aligned.m16n8k16.row.col.f32.bf16.bf16.f32 "
                 "{%0,%1,%2,%3}, {%4,%5,%6,%7}, {%8,%9}, {%0,%1,%2,%3};"
                 : "+f"(d[0]), "+f"(d[1]), "+f"(d[2]), "+f"(d[3])
                 : "r"(a[0]), "r"(a[1]), "r"(a[2]), "r"(a[3]),
                   "r"(b[0]), "r"(b[1]));
}

// ---------------------------------------------------------------------------
// Conversion kernels: fp32 -> bf16 hi/lo
// ---------------------------------------------------------------------------
__global__ __launch_bounds__(256) void convert_x_kernel(
    const float* __restrict__ q, const float* __restrict__ k,
    const float* __restrict__ v)
{
    const float* src = (blockIdx.y == 0) ? q : (blockIdx.y == 1) ? k : v;
    __nv_bfloat16* hi = g_Xhi + (size_t)blockIdx.y * MROWS * DMODEL;
    __nv_bfloat16* lo = g_Xlo + (size_t)blockIdx.y * MROWS * DMODEL;

    size_t i4 = (size_t)blockIdx.x * 256 + threadIdx.x;   // float4 index
    float4 x = ((const float4*)src)[i4];
    float xs[4] = {x.x, x.y, x.z, x.w};
    __nv_bfloat162 h2[2], l2[2];
#pragma unroll
    for (int t = 0; t < 2; t++) {
        __nv_bfloat16 h0 = __float2bfloat16(xs[2 * t]);
        __nv_bfloat16 h1 = __float2bfloat16(xs[2 * t + 1]);
        __nv_bfloat16 l0 = __float2bfloat16(xs[2 * t] - __bfloat162float(h0));
        __nv_bfloat16 l1 = __float2bfloat16(xs[2 * t + 1] - __bfloat162float(h1));
        h2[t].x = h0; h2[t].y = h1; l2[t].x = l0; l2[t].y = l1;
    }
    ((__nv_bfloat162*)hi)[i4 * 2 + 0] = h2[0];
    ((__nv_bfloat162*)hi)[i4 * 2 + 1] = h2[1];
    ((__nv_bfloat162*)lo)[i4 * 2 + 0] = l2[0];
    ((__nv_bfloat162*)lo)[i4 * 2 + 1] = l2[1];
}

__global__ __launch_bounds__(256) void convert_wt_kernel(
    const float* __restrict__ Wq, const float* __restrict__ Wk,
    const float* __restrict__ Wv, const float* __restrict__ Wo)
{
    const float* W = (blockIdx.z == 0) ? Wq : (blockIdx.z == 1) ? Wk
                   : (blockIdx.z == 2) ? Wv : Wo;
    __nv_bfloat16* hi = g_Wthi + (size_t)blockIdx.z * DMODEL * DMODEL;
    __nv_bfloat16* lo = g_Wtlo + (size_t)blockIdx.z * DMODEL * DMODEL;

    __shared__ float t[32][33];
    int tx = threadIdx.x & 31, ty = threadIdx.x >> 5;    // 32 x 8
    int k0 = blockIdx.y * 32, n0 = blockIdx.x * 32;
#pragma unroll
    for (int d = 0; d < 4; d++)
        t[ty + 8 * d][tx] = W[(size_t)(k0 + ty + 8 * d) * DMODEL + n0 + tx];
    __syncthreads();
#pragma unroll
    for (int d = 0; d < 4; d++) {
        float val = t[tx][ty + 8 * d];
        __nv_bfloat16 h = __float2bfloat16(val);
        __nv_bfloat16 l = __float2bfloat16(val - __bfloat162float(h));
        size_t o = (size_t)(n0 + ty + 8 * d) * DMODEL + k0 + tx;
        hi[o] = h; lo[o] = l;
    }
}

// ---------------------------------------------------------------------------
// Split-bf16 HMMA GEMM: C[M,N] = A[M,K] @ Bt[N,K]^T + bias
// CTA tile 128x128, BK=32, 8 warps (2m x 4n), warp tile 64x32.
// D += Ahi*Bhi + Ahi*Blo + Alo*Bhi  (fp32 mma accumulators)
// ---------------------------------------------------------------------------
#define BM 128
#define BN 128
#define BK 32
#define AST 40   // smem row stride in halves (80B: conflict-free ldmatrix)

struct GemmPtrs {
    const __nv_bfloat16 *Ahi, *Alo, *Bhi, *Blo;
    const float* bias;
    float* out;
};

__device__ __forceinline__ void gemm_body(const GemmPtrs& P, int m0, int n0,
                                          int proj_layout)
{
    __shared__ __nv_bfloat16 sAh[BM * AST];
    __shared__ __nv_bfloat16 sAl[BM * AST];
    __shared__ __nv_bfloat16 sBh[BN * AST];
    __shared__ __nv_bfloat16 sBl[BN * AST];

    const int tid = threadIdx.x;
    const int wid = tid >> 5;
    const int lane = tid & 31;
    const int wm = (wid & 1) * 64;       // warp m offset in tile
    const int wn = (wid >> 1) * 32;      // warp n offset in tile

    const uint32_t uAh = smem_u32(sAh);
    const uint32_t uAl = smem_u32(sAl);
    const uint32_t uBh = smem_u32(sBh);
    const uint32_t uBl = smem_u32(sBl);

    float acc[4][4][4];   // [mtile][ntile][frag]
#pragma unroll
    for (int i = 0; i < 4; i++)
#pragma unroll
        for (int j = 0; j < 4; j++)
#pragma unroll
            for (int f = 0; f < 4; f++) acc[i][j][f] = 0.f;

    // ldmatrix lane addressing (in halves)
    const int a_row = lane & 15;             // within m16
    const int a_k8  = (lane >> 4) * 8;       // 0 or 8
    const int b_lr  = lane & 7;
    const int b_g   = lane >> 3;             // 0..3
    const int b_nadd = (b_g & 2) * 4;        // 0 or 8
    const int b_kadd = (b_g & 1) * 8;        // 0 or 8

    for (int kt = 0; kt < DMODEL; kt += BK) {
        // stage A (128x32) and B (128x32), hi+lo: 512 uint4 each pair
        for (int idx = tid; idx < 512; idx += 256) {
            int r = idx >> 2, c4 = idx & 3;
            int soff = r * AST + c4 * 8;
            size_t ga = (size_t)(m0 + r) * DMODEL + kt + c4 * 8;
            size_t gb = (size_t)(n0 + r) * DMODEL + kt + c4 * 8;
            *(uint4*)&sAh[soff] = *(const uint4*)(P.Ahi + ga);
            *(uint4*)&sAl[soff] = *(const uint4*)(P.Alo + ga);
            *(uint4*)&sBh[soff] = *(const uint4*)(P.Bhi + gb);
            *(uint4*)&sBl[soff] = *(const uint4*)(P.Blo + gb);
        }
        __syncthreads();

#pragma unroll
        for (int kk = 0; kk < BK; kk += 16) {
            // B fragments: 2 pairs x (hi,lo), each x4 covers two n8 tiles
            uint32_t bh[2][4], bl[2][4];
#pragma unroll
            for (int p = 0; p < 2; p++) {
                uint32_t boff = ((wn + p * 16 + b_lr + b_nadd) * AST
                                 + kk + b_kadd) * 2;
                ldsm4(bh[p], uBh + boff);
                ldsm4(bl[p], uBl + boff);
            }
#pragma unroll
            for (int mt = 0; mt < 4; mt++) {
                uint32_t ah[4], al[4];
                uint32_t aoff = ((wm + mt * 16 + a_row) * AST + kk + a_k8) * 2;
                ldsm4(ah, uAh + aoff);
                ldsm4(al, uAl + aoff);
#pragma unroll
                for (int nt = 0; nt < 4; nt++) {
                    const uint32_t* fbh = &bh[nt >> 1][(nt & 1) * 2];
                    const uint32_t* fbl = &bl[nt >> 1][(nt & 1) * 2];
                    mma16816(acc[mt][nt], ah, fbh);
                    mma16816(acc[mt][nt], ah, fbl);
                    mma16816(acc[mt][nt], al, fbh);
                }
            }
        }
        __syncthreads();
    }

    // Epilogue: per (mt,nt) thread owns rows r,r+8 and cols n,n+1
    const int rbase = m0 + wm + (lane >> 2);
    const int cbase = n0 + wn + (lane & 3) * 2;
#pragma unroll
    for (int mt = 0; mt < 4; mt++) {
#pragma unroll
        for (int nt = 0; nt < 4; nt++) {
            int n = cbase + nt * 8;
            float b0 = P.bias[n], b1 = P.bias[n + 1];
#pragma unroll
            for (int half = 0; half < 2; half++) {
                int r = rbase + mt * 16 + half * 8;
                float2 w;
                w.x = acc[mt][nt][half * 2 + 0] + b0;
                w.y = acc[mt][nt][half * 2 + 1] + b1;
                float* dst;
                if (proj_layout) {
                    int b = r >> 11, ss = r & (SEQ - 1);
                    int h = n >> 6, dd = n & 63;
                    dst = P.out + (((size_t)(b * NHEAD + h) * SEQ + ss) * DHEAD + dd);
                } else {
                    dst = P.out + (size_t)r * DMODEL + n;
                }
                *(float2*)dst = w;
            }
        }
    }
}

__global__ __launch_bounds__(256) void gemm_qkv_kernel(
    const float* __restrict__ bq, const float* __restrict__ bk,
    const float* __restrict__ bv)
{
    int z = blockIdx.z;
    GemmPtrs P;
    P.Ahi = g_Xhi + (size_t)z * MROWS * DMODEL;
    P.Alo = g_Xlo + (size_t)z * MROWS * DMODEL;
    P.Bhi = g_Wthi + (size_t)z * DMODEL * DMODEL;
    P.Blo = g_Wtlo + (size_t)z * DMODEL * DMODEL;
    P.bias = (z == 0) ? bq : (z == 1) ? bk : bv;
    P.out  = (z == 0) ? g_Qh : (z == 1) ? g_Kh : g_Vh;
    gemm_body(P, blockIdx.y * BM, blockIdx.x * BN, 1);
}

__global__ __launch_bounds__(256) void gemm_out_kernel(
    const float* __restrict__ bo, float* __restrict__ out)
{
    GemmPtrs P;
    P.Ahi = g_Chi; P.Alo = g_Clo;
    P.Bhi = g_Wthi + (size_t)3 * DMODEL * DMODEL;
    P.Blo = g_Wtlo + (size_t)3 * DMODEL * DMODEL;
    P.bias = bo; P.out = out;
    gemm_body(P, blockIdx.y * BM, blockIdx.x * BN, 0);
}

// ---------------------------------------------------------------------------
// Flash attention (fp32), emits bf16 hi/lo ctx
// ---------------------------------------------------------------------------
#define QPAD 65
#define PPAD 33
__global__ __launch_bounds__(256) void attn_kernel(const int* __restrict__ mask)
{
    __shared__ float Qs[64 * QPAD];
    __shared__ float Ks[32 * QPAD];
    __shared__ float Vs[32 * QPAD];
    __shared__ float Ps[64 * PPAD];

    const int bh = blockIdx.y;
    const int b = bh >> 4;
    const int h = bh & 15;
    const int qt = blockIdx.x;
    const int tid = threadIdx.x;
    const int ty = tid >> 4, tx = tid & 15;

    const float* Qbase = g_Qh + ((size_t)bh * SEQ + qt * 64) * DHEAD;
    const float* Kbase = g_Kh + (size_t)bh * SEQ * DHEAD;
    const float* Vbase = g_Vh + (size_t)bh * SEQ * DHEAD;
    const int* mrow = mask + b * SEQ;

    for (int i = tid; i < 64 * 64; i += 256) {
        int r = i >> 6, c = i & 63;
        Qs[r * QPAD + c] = Qbase[i];
    }

    float m_i[4], l_i[4], O[4][4];
#pragma unroll
    for (int i = 0; i < 4; i++) {
        m_i[i] = -1e30f; l_i[i] = 0.f;
#pragma unroll
        for (int j = 0; j < 4; j++) O[i][j] = 0.f;
    }
    __syncthreads();

    for (int kt = 0; kt < SEQ; kt += 32) {
        for (int i = tid; i < 32 * 64; i += 256) {
            int r = i >> 6, c = i & 63;
            Ks[r * QPAD + c] = Kbase[(size_t)(kt + r) * DHEAD + c];
            Vs[r * QPAD + c] = Vbase[(size_t)(kt + r) * DHEAD + c];
        }
        __syncthreads();

        float s[4][2];
#pragma unroll
        for (int i = 0; i < 4; i++) { s[i][0] = 0.f; s[i][1] = 0.f; }

#pragma unroll 8
        for (int kk = 0; kk < 64; kk++) {
            float ra[4], rb[2];
#pragma unroll
            for (int i = 0; i < 4; i++) ra[i] = Qs[(ty * 4 + i) * QPAD + kk];
            rb[0] = Ks[(tx * 2 + 0) * QPAD + kk];
            rb[1] = Ks[(tx * 2 + 1) * QPAD + kk];
#pragma unroll
            for (int i = 0; i < 4; i++) {
                s[i][0] = fmaf(ra[i], rb[0], s[i][0]);
                s[i][1] = fmaf(ra[i], rb[1], s[i][1]);
            }
        }

        float cb0 = (float)mrow[kt + tx * 2 + 0] * (-1000000000.0f);
        float cb1 = (float)mrow[kt + tx * 2 + 1] * (-1000000000.0f);
#pragma unroll
        for (int i = 0; i < 4; i++) {
            s[i][0] = s[i][0] * 0.125f + cb0;
            s[i][1] = s[i][1] * 0.125f + cb1;
        }

        float mnew[4];
#pragma unroll
        for (int i = 0; i < 4; i++) {
            float t = fmaxf(s[i][0], s[i][1]);
#pragma unroll
            for (int o = 8; o >= 1; o >>= 1)
                t = fmaxf(t, __shfl_xor_sync(0xffffffffu, t, o));
            mnew[i] = fmaxf(m_i[i], t);
        }

        float rowsum[4];
#pragma unroll
        for (int i = 0; i < 4; i++) {
            s[i][0] = __expf(s[i][0] - mnew[i]);
            s[i][1] = __expf(s[i][1] - mnew[i]);
            float rs = s[i][0] + s[i][1];
#pragma unroll
            for (int o = 8; o >= 1; o >>= 1)
                rs += __shfl_xor_sync(0xffffffffu, rs, o);
            rowsum[i] = rs;
        }
#pragma unroll
        for (int i = 0; i < 4; i++) {
            float alpha = __expf(m_i[i] - mnew[i]);
            l_i[i] = l_i[i] * alpha + rowsum[i];
            m_i[i] = mnew[i];
#pragma unroll
            for (int j = 0; j < 4; j++) O[i][j] *= alpha;
        }

#pragma unroll
        for (int i = 0; i < 4; i++) {
            Ps[(ty * 4 + i) * PPAD + tx * 2 + 0] = s[i][0];
            Ps[(ty * 4 + i) * PPAD + tx * 2 + 1] = s[i][1];
        }
        __syncthreads();

#pragma unroll 8
        for (int j = 0; j < 32; j++) {
            float pr[4], vr[4];
#pragma unroll
            for (int i = 0; i < 4; i++) pr[i] = Ps[(ty * 4 + i) * PPAD + j];
#pragma unroll
            for (int jj = 0; jj < 4; jj++) vr[jj] = Vs[j * QPAD + tx * 4 + jj];
#pragma unroll
            for (int i = 0; i < 4; i++)
#pragma unroll
                for (int jj = 0; jj < 4; jj++)
                    O[i][jj] = fmaf(pr[i], vr[jj], O[i][jj]);
        }
        __syncthreads();
    }

    // ctx -> bf16 hi/lo in [B,S,D] layout
#pragma unroll
    for (int i = 0; i < 4; i++) {
        int row = qt * 64 + ty * 4 + i;
        float inv = 1.0f / l_i[i];
#pragma unroll
        for (int j = 0; j < 4; j++) {
            int col = h * DHEAD + tx * 4 + j;
            float val = O[i][j] * inv;
            __nv_bfloat16 hv = __float2bfloat16(val);
            __nv_bfloat16 lv = __float2bfloat16(val - __bfloat162float(hv));
            size_t o = ((size_t)b * SEQ + row) * DMODEL + col;
            g_Chi[o] = hv;
            g_Clo[o] = lv;
        }
    }
}

// ---------------------------------------------------------------------------
// Launch: pure kernel launches only
// ---------------------------------------------------------------------------
extern "C" void kernel_launch(void* const* d_in, const int* in_sizes, int n_in,
                              void* d_out, int out_size)
{
    const float* v  = (const float*)d_in[0];
    const float* k  = (const float*)d_in[1];
    const float* q  = (const float*)d_in[2];
    const int*   mask = (const int*)d_in[3];
    const float* Wq = (const float*)d_in[4];
    const float* bq = (const float*)d_in[5];
    const float* Wk = (const float*)d_in[6];
    const float* bk = (const float*)d_in[7];
    const float* Wv = (const float*)d_in[8];
    const float* bv = (const float*)d_in[9];
    const float* Wo = (const float*)d_in[10];
    const float* bo = (const float*)d_in[11];
    float* out = (float*)d_out;

    // fp32 -> bf16 hi/lo conversions
    convert_x_kernel<<<dim3(MROWS * DMODEL / 4 / 256, 3), 256>>>(q, k, v);
    convert_wt_kernel<<<dim3(32, 32, 4), 256>>>(Wq, Wk, Wv, Wo);

    // QKV projection GEMMs (HMMA split-bf16)
    gemm_qkv_kernel<<<dim3(DMODEL / BN, MROWS / BM, 3), 256>>>(bq, bk, bv);

    // Flash attention (fp32)
    attn_kernel<<<dim3(SEQ / 64, BB * NHEAD), 256>>>(mask);

    // Output projection GEMM
    gemm_out_kernel<<<dim3(DMODEL / BN, MROWS / BM), 256>>>(bo, out);
}

// round 9
// speedup vs baseline: 2.6225x; 1.9228x over previous
#include <cuda_runtime.h>
#include <cuda_bf16.h>
#include <cstdint>
#include <math.h>

// Problem constants
#define BB 4
#define SEQ 2048
#define DMODEL 1024
#define NHEAD 16
#define DHEAD 64
#define MROWS (BB * SEQ)   // 8192

// ---------------------------------------------------------------------------
// Device-global scratch (allocation is forbidden)
// ---------------------------------------------------------------------------
__device__ __nv_bfloat16 g_Xhi[3 * MROWS * DMODEL];   // q,k,v inputs [M,K]
__device__ __nv_bfloat16 g_Xlo[3 * MROWS * DMODEL];
__device__ __nv_bfloat16 g_Wthi[4 * DMODEL * DMODEL]; // W transposed [N,K]
__device__ __nv_bfloat16 g_Wtlo[4 * DMODEL * DMODEL];

__device__ __nv_bfloat16 g_Qhi[BB * NHEAD * SEQ * DHEAD];  // [B,H,S,d]
__device__ __nv_bfloat16 g_Qlo[BB * NHEAD * SEQ * DHEAD];
__device__ __nv_bfloat16 g_Khi[BB * NHEAD * SEQ * DHEAD];  // [B,H,S,d]
__device__ __nv_bfloat16 g_Klo[BB * NHEAD * SEQ * DHEAD];
__device__ __nv_bfloat16 g_Vthi[BB * NHEAD * DHEAD * SEQ]; // [B,H,d,S] transposed
__device__ __nv_bfloat16 g_Vtlo[BB * NHEAD * DHEAD * SEQ];

__device__ __nv_bfloat16 g_Chi[MROWS * DMODEL];            // ctx [B,S,D]
__device__ __nv_bfloat16 g_Clo[MROWS * DMODEL];

// ---------------------------------------------------------------------------
// mma.sync / ldmatrix helpers (baseline PTX, legal on plain sm_103 target)
// ---------------------------------------------------------------------------
__device__ __forceinline__ uint32_t smem_u32(const void* p) {
    uint32_t a;
    asm("{ .reg .u64 t; cvta.to.shared.u64 t, %1; cvt.u32.u64 %0, t; }"
        : "=r"(a) : "l"(p));
    return a;
}
__device__ __forceinline__ void ldsm4(uint32_t* r, uint32_t addr) {
    asm volatile("ldmatrix.sync.aligned.m8n8.x4.shared.b16 {%0,%1,%2,%3}, [%4];"
                 : "=r"(r[0]), "=r"(r[1]), "=r"(r[2]), "=r"(r[3]) : "r"(addr));
}
__device__ __forceinline__ void mma16816(float* d, const uint32_t* a, const uint32_t* b) {
    asm volatile("mma.sync.aligned.m16n8k16.row.col.f32.bf16.bf16.f32 "
                 "{%0,%1,%2,%3}, {%4,%5,%6,%7}, {%8,%9}, {%0,%1,%2,%3};"
                 : "+f"(d[0]), "+f"(d[1]), "+f"(d[2]), "+f"(d[3])
                 : "r"(a[0]), "r"(a[1]), "r"(a[2]), "r"(a[3]),
                   "r"(b[0]), "r"(b[1]));
}
__device__ __forceinline__ uint32_t pack_bf2(__nv_bfloat16 a, __nv_bfloat16 b) {
    __nv_bfloat162 t; t.x = a; t.y = b;
    return *reinterpret_cast<uint32_t*>(&t);
}
// split a pair of floats into bf16 hi/lo packed registers
__device__ __forceinline__ void split2(float x, float y, uint32_t& hi, uint32_t& lo) {
    __nv_bfloat16 hx = __float2bfloat16(x);
    __nv_bfloat16 hy = __float2bfloat16(y);
    hi = pack_bf2(hx, hy);
    lo = pack_bf2(__float2bfloat16(x - __bfloat162float(hx)),
                  __float2bfloat16(y - __bfloat162float(hy)));
}

// ---------------------------------------------------------------------------
// Conversion kernels: fp32 -> bf16 hi/lo
// ---------------------------------------------------------------------------
__global__ __launch_bounds__(256) void convert_x_kernel(
    const float* __restrict__ q, const float* __restrict__ k,
    const float* __restrict__ v)
{
    const float* src = (blockIdx.y == 0) ? q : (blockIdx.y == 1) ? k : v;
    __nv_bfloat16* hi = g_Xhi + (size_t)blockIdx.y * MROWS * DMODEL;
    __nv_bfloat16* lo = g_Xlo + (size_t)blockIdx.y * MROWS * DMODEL;

    size_t i4 = (size_t)blockIdx.x * 256 + threadIdx.x;
    float4 x = ((const float4*)src)[i4];
    float xs[4] = {x.x, x.y, x.z, x.w};
    uint32_t h2[2], l2[2];
    split2(xs[0], xs[1], h2[0], l2[0]);
    split2(xs[2], xs[3], h2[1], l2[1]);
    ((uint32_t*)hi)[i4 * 2 + 0] = h2[0];
    ((uint32_t*)hi)[i4 * 2 + 1] = h2[1];
    ((uint32_t*)lo)[i4 * 2 + 0] = l2[0];
    ((uint32_t*)lo)[i4 * 2 + 1] = l2[1];
}

__global__ __launch_bounds__(256) void convert_wt_kernel(
    const float* __restrict__ Wq, const float* __restrict__ Wk,
    const float* __restrict__ Wv, const float* __restrict__ Wo)
{
    const float* W = (blockIdx.z == 0) ? Wq : (blockIdx.z == 1) ? Wk
                   : (blockIdx.z == 2) ? Wv : Wo;
    __nv_bfloat16* hi = g_Wthi + (size_t)blockIdx.z * DMODEL * DMODEL;
    __nv_bfloat16* lo = g_Wtlo + (size_t)blockIdx.z * DMODEL * DMODEL;

    __shared__ float t[32][33];
    int tx = threadIdx.x & 31, ty = threadIdx.x >> 5;    // 32 x 8
    int k0 = blockIdx.y * 32, n0 = blockIdx.x * 32;
#pragma unroll
    for (int d = 0; d < 4; d++)
        t[ty + 8 * d][tx] = W[(size_t)(k0 + ty + 8 * d) * DMODEL + n0 + tx];
    __syncthreads();
#pragma unroll
    for (int d = 0; d < 4; d++) {
        float val = t[tx][ty + 8 * d];
        __nv_bfloat16 h = __float2bfloat16(val);
        __nv_bfloat16 l = __float2bfloat16(val - __bfloat162float(h));
        size_t o = (size_t)(n0 + ty + 8 * d) * DMODEL + k0 + tx;
        hi[o] = h; lo[o] = l;
    }
}

// ---------------------------------------------------------------------------
// Split-bf16 HMMA GEMM. CTA 128x128, BK=32, 8 warps (2m x 4n).
// mode 0: fp32 out [M,DMODEL]; mode 1: bf16 hi/lo [B,H,S,d];
// mode 2: bf16 hi/lo transposed [B,H,d,S]
// ---------------------------------------------------------------------------
#define BM 128
#define BN 128
#define BK 32
#define AST 40

struct GemmPtrs {
    const __nv_bfloat16 *Ahi, *Alo, *Bhi, *Blo;
    const float* bias;
    float* out;
    __nv_bfloat16 *Ohi, *Olo;
};

__device__ __forceinline__ void gemm_body(const GemmPtrs& P, int m0, int n0,
                                          int mode)
{
    __shared__ __nv_bfloat16 sAh[BM * AST];
    __shared__ __nv_bfloat16 sAl[BM * AST];
    __shared__ __nv_bfloat16 sBh[BN * AST];
    __shared__ __nv_bfloat16 sBl[BN * AST];

    const int tid = threadIdx.x;
    const int wid = tid >> 5;
    const int lane = tid & 31;
    const int wm = (wid & 1) * 64;
    const int wn = (wid >> 1) * 32;

    const uint32_t uAh = smem_u32(sAh);
    const uint32_t uAl = smem_u32(sAl);
    const uint32_t uBh = smem_u32(sBh);
    const uint32_t uBl = smem_u32(sBl);

    float acc[4][4][4];
#pragma unroll
    for (int i = 0; i < 4; i++)
#pragma unroll
        for (int j = 0; j < 4; j++)
#pragma unroll
            for (int f = 0; f < 4; f++) acc[i][j][f] = 0.f;

    const int a_row = lane & 15;
    const int a_k8  = (lane >> 4) * 8;
    const int b_lr  = lane & 7;
    const int b_g   = lane >> 3;
    const int b_nadd = (b_g & 2) * 4;
    const int b_kadd = (b_g & 1) * 8;

    for (int kt = 0; kt < DMODEL; kt += BK) {
        for (int idx = tid; idx < 512; idx += 256) {
            int r = idx >> 2, c4 = idx & 3;
            int soff = r * AST + c4 * 8;
            size_t ga = (size_t)(m0 + r) * DMODEL + kt + c4 * 8;
            size_t gb = (size_t)(n0 + r) * DMODEL + kt + c4 * 8;
            *(uint4*)&sAh[soff] = *(const uint4*)(P.Ahi + ga);
            *(uint4*)&sAl[soff] = *(const uint4*)(P.Alo + ga);
            *(uint4*)&sBh[soff] = *(const uint4*)(P.Bhi + gb);
            *(uint4*)&sBl[soff] = *(const uint4*)(P.Blo + gb);
        }
        __syncthreads();

#pragma unroll
        for (int kk = 0; kk < BK; kk += 16) {
            uint32_t bh[2][4], bl[2][4];
#pragma unroll
            for (int p = 0; p < 2; p++) {
                uint32_t boff = ((wn + p * 16 + b_lr + b_nadd) * AST
                                 + kk + b_kadd) * 2;
                ldsm4(bh[p], uBh + boff);
                ldsm4(bl[p], uBl + boff);
            }
#pragma unroll
            for (int mt = 0; mt < 4; mt++) {
                uint32_t ah[4], al[4];
                uint32_t aoff = ((wm + mt * 16 + a_row) * AST + kk + a_k8) * 2;
                ldsm4(ah, uAh + aoff);
                ldsm4(al, uAl + aoff);
#pragma unroll
                for (int nt = 0; nt < 4; nt++) {
                    const uint32_t* fbh = &bh[nt >> 1][(nt & 1) * 2];
                    const uint32_t* fbl = &bl[nt >> 1][(nt & 1) * 2];
                    mma16816(acc[mt][nt], ah, fbh);
                    mma16816(acc[mt][nt], ah, fbl);
                    mma16816(acc[mt][nt], al, fbh);
                }
            }
        }
        __syncthreads();
    }

    const int rbase = m0 + wm + (lane >> 2);
    const int cbase = n0 + wn + (lane & 3) * 2;
#pragma unroll
    for (int mt = 0; mt < 4; mt++) {
#pragma unroll
        for (int nt = 0; nt < 4; nt++) {
            int n = cbase + nt * 8;
            float b0 = P.bias[n], b1 = P.bias[n + 1];
#pragma unroll
            for (int half = 0; half < 2; half++) {
                int r = rbase + mt * 16 + half * 8;
                float wx = acc[mt][nt][half * 2 + 0] + b0;
                float wy = acc[mt][nt][half * 2 + 1] + b1;
                if (mode == 0) {
                    float2 w2; w2.x = wx; w2.y = wy;
                    *(float2*)(P.out + (size_t)r * DMODEL + n) = w2;
                } else {
                    int b = r >> 11, ss = r & (SEQ - 1);
                    int h = n >> 6, dd = n & 63;
                    int bhh = b * NHEAD + h;
                    uint32_t hv, lv;
                    split2(wx, wy, hv, lv);
                    if (mode == 1) {
                        size_t o = ((size_t)bhh * SEQ + ss) * DHEAD + dd;
                        *(uint32_t*)(P.Ohi + o) = hv;
                        *(uint32_t*)(P.Olo + o) = lv;
                    } else {
                        // transposed [B,H,d,S]
                        __nv_bfloat162 h2 = *reinterpret_cast<__nv_bfloat162*>(&hv);
                        __nv_bfloat162 l2 = *reinterpret_cast<__nv_bfloat162*>(&lv);
                        size_t o0 = ((size_t)bhh * DHEAD + dd) * SEQ + ss;
                        size_t o1 = ((size_t)bhh * DHEAD + dd + 1) * SEQ + ss;
                        P.Ohi[o0] = h2.x; P.Ohi[o1] = h2.y;
                        P.Olo[o0] = l2.x; P.Olo[o1] = l2.y;
                    }
                }
            }
        }
    }
}

__global__ __launch_bounds__(256) void gemm_qkv_kernel(
    const float* __restrict__ bq, const float* __restrict__ bk,
    const float* __restrict__ bv)
{
    int z = blockIdx.z;
    GemmPtrs P;
    P.Ahi = g_Xhi + (size_t)z * MROWS * DMODEL;
    P.Alo = g_Xlo + (size_t)z * MROWS * DMODEL;
    P.Bhi = g_Wthi + (size_t)z * DMODEL * DMODEL;
    P.Blo = g_Wtlo + (size_t)z * DMODEL * DMODEL;
    P.bias = (z == 0) ? bq : (z == 1) ? bk : bv;
    P.out = 0;
    P.Ohi = (z == 0) ? g_Qhi : (z == 1) ? g_Khi : g_Vthi;
    P.Olo = (z == 0) ? g_Qlo : (z == 1) ? g_Klo : g_Vtlo;
    gemm_body(P, blockIdx.y * BM, blockIdx.x * BN, (z == 2) ? 2 : 1);
}

__global__ __launch_bounds__(256) void gemm_out_kernel(
    const float* __restrict__ bo, float* __restrict__ out)
{
    GemmPtrs P;
    P.Ahi = g_Chi; P.Alo = g_Clo;
    P.Bhi = g_Wthi + (size_t)3 * DMODEL * DMODEL;
    P.Blo = g_Wtlo + (size_t)3 * DMODEL * DMODEL;
    P.bias = bo; P.out = out; P.Ohi = 0; P.Olo = 0;
    gemm_body(P, blockIdx.y * BM, blockIdx.x * BN, 0);
}

// ---------------------------------------------------------------------------
// Tensor-core flash attention. Block: 128 q-rows x one (b,h). 8 warps x 16 rows.
// K tiles of 64. Split-bf16: 3 mma products per logical product.
// smem 36,864 B static + mask.
// ---------------------------------------------------------------------------
#define TST 72   // smem row stride in halves

__global__ __launch_bounds__(256) void attn_kernel(const int* __restrict__ mask)
{
    __shared__ __nv_bfloat16 sm[4 * 64 * TST];   // 4 regions of 64x72 halves
    __shared__ float sMask[64];

    __nv_bfloat16* sKh = sm;                    // K hi  (region 0)
    __nv_bfloat16* sKl = sm + 64 * TST;         // K lo  (region 1)
    __nv_bfloat16* sVh = sm + 2 * 64 * TST;     // Vt hi (region 2)
    __nv_bfloat16* sVl = sm + 3 * 64 * TST;     // Vt lo (region 3)
    // Q staging reuses regions 0-1 (hi) and 2-3 (lo): 128x72 halves each

    const int bh = blockIdx.y;
    const int b = bh >> 4;
    const int h = bh & 15;
    const int q0 = blockIdx.x * 128;
    const int tid = threadIdx.x;
    const int wid = tid >> 5;
    const int lane = tid & 31;
    const int wm = wid * 16;

    const __nv_bfloat16* Qhi = g_Qhi + ((size_t)bh * SEQ + q0) * DHEAD;
    const __nv_bfloat16* Qlo = g_Qlo + ((size_t)bh * SEQ + q0) * DHEAD;
    const __nv_bfloat16* Khi = g_Khi + (size_t)bh * SEQ * DHEAD;
    const __nv_bfloat16* Klo = g_Klo + (size_t)bh * SEQ * DHEAD;
    const __nv_bfloat16* Vth = g_Vthi + (size_t)bh * DHEAD * SEQ;
    const __nv_bfloat16* Vtl = g_Vtlo + (size_t)bh * DHEAD * SEQ;
    const int* mrow = mask + b * SEQ;

    const int a_row = lane & 15;
    const int a_k8  = (lane >> 4) * 8;
    const int b_lr  = lane & 7;
    const int b_g   = lane >> 3;
    const int b_nadd = (b_g & 2) * 4;
    const int b_kadd = (b_g & 1) * 8;

    // ---- stage Q (128 x 64 hi/lo) into smem, load fragments, release smem
    for (int idx = tid; idx < 1024; idx += 256) {
        int r = idx >> 3, c8 = idx & 7;
        int soff = r * TST + c8 * 8;
        size_t g = (size_t)r * DHEAD + c8 * 8;
        *(uint4*)&sm[soff]            = *(const uint4*)(Qhi + g);
        *(uint4*)&sm[2 * 64 * TST + soff] = *(const uint4*)(Qlo + g);
    }
    __syncthreads();

    uint32_t qh[4][4], ql[4][4];
    {
        uint32_t uQh = smem_u32(sm);
        uint32_t uQl = smem_u32(sm + 2 * 64 * TST);
#pragma unroll
        for (int kc = 0; kc < 4; kc++) {
            uint32_t aoff = ((wm + a_row) * TST + kc * 16 + a_k8) * 2;
            ldsm4(qh[kc], uQh + aoff);
            ldsm4(ql[kc], uQl + aoff);
        }
    }
    __syncthreads();

    const uint32_t uKh = smem_u32(sKh);
    const uint32_t uKl = smem_u32(sKl);
    const uint32_t uVh = smem_u32(sVh);
    const uint32_t uVl = smem_u32(sVl);

    float O[8][4];
#pragma unroll
    for (int i = 0; i < 8; i++)
#pragma unroll
        for (int j = 0; j < 4; j++) O[i][j] = 0.f;
    float m_i[2] = {-1e30f, -1e30f};
    float l_i[2] = {0.f, 0.f};

    for (int kt = 0; kt < SEQ; kt += 64) {
        if (tid < 64) sMask[tid] = (float)mrow[kt + tid] * (-1000000000.0f);
        // stage K (64x64) and Vt (64x64), hi/lo
        for (int idx = tid; idx < 512; idx += 256) {
            int r = idx >> 3, c8 = idx & 7;
            int soff = r * TST + c8 * 8;
            size_t gk = (size_t)(kt + r) * DHEAD + c8 * 8;
            size_t gv = (size_t)r * SEQ + kt + c8 * 8;
            *(uint4*)&sKh[soff] = *(const uint4*)(Khi + gk);
            *(uint4*)&sKl[soff] = *(const uint4*)(Klo + gk);
            *(uint4*)&sVh[soff] = *(const uint4*)(Vth + gv);
            *(uint4*)&sVl[soff] = *(const uint4*)(Vtl + gv);
        }
        __syncthreads();

        // ---- S = Q K^T (16 x 64 per warp), split 3-product
        float s[8][4];
#pragma unroll
        for (int i = 0; i < 8; i++)
#pragma unroll
            for (int j = 0; j < 4; j++) s[i][j] = 0.f;

#pragma unroll
        for (int kc = 0; kc < 4; kc++) {
            uint32_t kbh[4][4], kbl[4][4];
#pragma unroll
            for (int p = 0; p < 4; p++) {
                uint32_t boff = ((p * 16 + b_lr + b_nadd) * TST
                                 + kc * 16 + b_kadd) * 2;
                ldsm4(kbh[p], uKh + boff);
                ldsm4(kbl[p], uKl + boff);
            }
#pragma unroll
            for (int nt = 0; nt < 8; nt++) {
                const uint32_t* fbh = &kbh[nt >> 1][(nt & 1) * 2];
                const uint32_t* fbl = &kbl[nt >> 1][(nt & 1) * 2];
                mma16816(s[nt], qh[kc], fbh);
                mma16816(s[nt], qh[kc], fbl);
                mma16816(s[nt], ql[kc], fbh);
            }
        }

        // ---- scale + mask
        const int c0 = (lane & 3) * 2;
#pragma unroll
        for (int nt = 0; nt < 8; nt++) {
            float bias0 = sMask[nt * 8 + c0];
            float bias1 = sMask[nt * 8 + c0 + 1];
            s[nt][0] = s[nt][0] * 0.125f + bias0;
            s[nt][1] = s[nt][1] * 0.125f + bias1;
            s[nt][2] = s[nt][2] * 0.125f + bias0;
            s[nt][3] = s[nt][3] * 0.125f + bias1;
        }

        // ---- online softmax on fragments (rows r0=lane>>2, r1=r0+8)
        float mx0 = -1e30f, mx1 = -1e30f;
#pragma unroll
        for (int nt = 0; nt < 8; nt++) {
            mx0 = fmaxf(mx0, fmaxf(s[nt][0], s[nt][1]));
            mx1 = fmaxf(mx1, fmaxf(s[nt][2], s[nt][3]));
        }
        mx0 = fmaxf(mx0, __shfl_xor_sync(0xffffffffu, mx0, 1));
        mx0 = fmaxf(mx0, __shfl_xor_sync(0xffffffffu, mx0, 2));
        mx1 = fmaxf(mx1, __shfl_xor_sync(0xffffffffu, mx1, 1));
        mx1 = fmaxf(mx1, __shfl_xor_sync(0xffffffffu, mx1, 2));
        float mnew0 = fmaxf(m_i[0], mx0);
        float mnew1 = fmaxf(m_i[1], mx1);

        float rs0 = 0.f, rs1 = 0.f;
#pragma unroll
        for (int nt = 0; nt < 8; nt++) {
            s[nt][0] = __expf(s[nt][0] - mnew0);
            s[nt][1] = __expf(s[nt][1] - mnew0);
            s[nt][2] = __expf(s[nt][2] - mnew1);
            s[nt][3] = __expf(s[nt][3] - mnew1);
            rs0 += s[nt][0] + s[nt][1];
            rs1 += s[nt][2] + s[nt][3];
        }
        rs0 += __shfl_xor_sync(0xffffffffu, rs0, 1);
        rs0 += __shfl_xor_sync(0xffffffffu, rs0, 2);
        rs1 += __shfl_xor_sync(0xffffffffu, rs1, 1);
        rs1 += __shfl_xor_sync(0xffffffffu, rs1, 2);

        float alpha0 = __expf(m_i[0] - mnew0);
        float alpha1 = __expf(m_i[1] - mnew1);
        l_i[0] = l_i[0] * alpha0 + rs0;
        l_i[1] = l_i[1] * alpha1 + rs1;
        m_i[0] = mnew0; m_i[1] = mnew1;
#pragma unroll
        for (int nt = 0; nt < 8; nt++) {
            O[nt][0] *= alpha0; O[nt][1] *= alpha0;
            O[nt][2] *= alpha1; O[nt][3] *= alpha1;
        }

        // ---- P fragments (C-layout -> A-layout, registers only)
        uint32_t ph[4][4], pl[4][4];
#pragma unroll
        for (int kc = 0; kc < 4; kc++) {
            int n0t = 2 * kc, n1t = 2 * kc + 1;
            split2(s[n0t][0], s[n0t][1], ph[kc][0], pl[kc][0]);
            split2(s[n0t][2], s[n0t][3], ph[kc][1], pl[kc][1]);
            split2(s[n1t][0], s[n1t][1], ph[kc][2], pl[kc][2]);
            split2(s[n1t][2], s[n1t][3], ph[kc][3], pl[kc][3]);
        }

        // ---- O += P V (contraction over 64 keys)
#pragma unroll
        for (int kc = 0; kc < 4; kc++) {
            uint32_t vbh[4][4], vbl[4][4];
#pragma unroll
            for (int p = 0; p < 4; p++) {
                uint32_t boff = ((p * 16 + b_lr + b_nadd) * TST
                                 + kc * 16 + b_kadd) * 2;
                ldsm4(vbh[p], uVh + boff);
                ldsm4(vbl[p], uVl + boff);
            }
#pragma unroll
            for (int nt = 0; nt < 8; nt++) {
                const uint32_t* fbh = &vbh[nt >> 1][(nt & 1) * 2];
                const uint32_t* fbl = &vbl[nt >> 1][(nt & 1) * 2];
                mma16816(O[nt], ph[kc], fbh);
                mma16816(O[nt], ph[kc], fbl);
                mma16816(O[nt], pl[kc], fbh);
            }
        }
        __syncthreads();
    }

    // ---- finalize and write ctx hi/lo in [B,S,D] layout
    float inv0 = 1.0f / l_i[0];
    float inv1 = 1.0f / l_i[1];
    int r0g = q0 + wm + (lane >> 2);
    int r1g = r0g + 8;
#pragma unroll
    for (int nt = 0; nt < 8; nt++) {
        int col = h * DHEAD + nt * 8 + (lane & 3) * 2;
        uint32_t hv, lv;
        split2(O[nt][0] * inv0, O[nt][1] * inv0, hv, lv);
        size_t o0 = ((size_t)b * SEQ + r0g) * DMODEL + col;
        *(uint32_t*)(g_Chi + o0) = hv;
        *(uint32_t*)(g_Clo + o0) = lv;
        split2(O[nt][2] * inv1, O[nt][3] * inv1, hv, lv);
        size_t o1 = ((size_t)b * SEQ + r1g) * DMODEL + col;
        *(uint32_t*)(g_Chi + o1) = hv;
        *(uint32_t*)(g_Clo + o1) = lv;
    }
}

// ---------------------------------------------------------------------------
// Launch: pure kernel launches only
// ---------------------------------------------------------------------------
extern "C" void kernel_launch(void* const* d_in, const int* in_sizes, int n_in,
                              void* d_out, int out_size)
{
    const float* v  = (const float*)d_in[0];
    const float* k  = (const float*)d_in[1];
    const float* q  = (const float*)d_in[2];
    const int*   mask = (const int*)d_in[3];
    const float* Wq = (const float*)d_in[4];
    const float* bq = (const float*)d_in[5];
    const float* Wk = (const float*)d_in[6];
    const float* bk = (const float*)d_in[7];
    const float* Wv = (const float*)d_in[8];
    const float* bv = (const float*)d_in[9];
    const float* Wo = (const float*)d_in[10];
    const float* bo = (const float*)d_in[11];
    float* out = (float*)d_out;

    convert_x_kernel<<<dim3(MROWS * DMODEL / 4 / 256, 3), 256>>>(q, k, v);
    convert_wt_kernel<<<dim3(32, 32, 4), 256>>>(Wq, Wk, Wv, Wo);

    gemm_qkv_kernel<<<dim3(DMODEL / BN, MROWS / BM, 3), 256>>>(bq, bk, bv);

    attn_kernel<<<dim3(SEQ / 128, BB * NHEAD), 256>>>(mask);

    gemm_out_kernel<<<dim3(DMODEL / BN, MROWS / BM), 256>>>(bo, out);
}

// round 10
// speedup vs baseline: 3.3209x; 1.2663x over previous
#include <cuda_runtime.h>
#include <cuda_bf16.h>
#include <cstdint>
#include <math.h>

// Problem constants
#define BB 4
#define SEQ 2048
#define DMODEL 1024
#define NHEAD 16
#define DHEAD 64
#define MROWS (BB * SEQ)   // 8192

// ---------------------------------------------------------------------------
// Device-global scratch (allocation is forbidden)
// ---------------------------------------------------------------------------
__device__ __nv_bfloat16 g_Xhi[3 * MROWS * DMODEL];   // q,k,v inputs [M,K]
__device__ __nv_bfloat16 g_Xlo[3 * MROWS * DMODEL];
__device__ __nv_bfloat16 g_Wthi[4 * DMODEL * DMODEL]; // W transposed [N,K]
__device__ __nv_bfloat16 g_Wtlo[4 * DMODEL * DMODEL];

__device__ __nv_bfloat16 g_Qhi[BB * NHEAD * SEQ * DHEAD];  // [B,H,S,d]
__device__ __nv_bfloat16 g_Qlo[BB * NHEAD * SEQ * DHEAD];
__device__ __nv_bfloat16 g_Khi[BB * NHEAD * SEQ * DHEAD];  // [B,H,S,d]
__device__ __nv_bfloat16 g_Klo[BB * NHEAD * SEQ * DHEAD];
__device__ __nv_bfloat16 g_Vthi[BB * NHEAD * DHEAD * SEQ]; // [B,H,d,S] transposed
__device__ __nv_bfloat16 g_Vtlo[BB * NHEAD * DHEAD * SEQ];

__device__ __nv_bfloat16 g_Chi[MROWS * DMODEL];            // ctx [B,S,D]
__device__ __nv_bfloat16 g_Clo[MROWS * DMODEL];

// ---------------------------------------------------------------------------
// mma.sync / ldmatrix / cp.async helpers (baseline PTX, plain sm_103 target)
// ---------------------------------------------------------------------------
__device__ __forceinline__ uint32_t smem_u32(const void* p) {
    uint32_t a;
    asm("{ .reg .u64 t; cvta.to.shared.u64 t, %1; cvt.u32.u64 %0, t; }"
        : "=r"(a) : "l"(p));
    return a;
}
__device__ __forceinline__ void ldsm4(uint32_t* r, uint32_t addr) {
    asm volatile("ldmatrix.sync.aligned.m8n8.x4.shared.b16 {%0,%1,%2,%3}, [%4];"
                 : "=r"(r[0]), "=r"(r[1]), "=r"(r[2]), "=r"(r[3]) : "r"(addr));
}
__device__ __forceinline__ void mma16816(float* d, const uint32_t* a, const uint32_t* b) {
    asm volatile("mma.sync.aligned.m16n8k16.row.col.f32.bf16.bf16.f32 "
                 "{%0,%1,%2,%3}, {%4,%5,%6,%7}, {%8,%9}, {%0,%1,%2,%3};"
                 : "+f"(d[0]), "+f"(d[1]), "+f"(d[2]), "+f"(d[3])
                 : "r"(a[0]), "r"(a[1]), "r"(a[2]), "r"(a[3]),
                   "r"(b[0]), "r"(b[1]));
}
__device__ __forceinline__ void cp16(uint32_t saddr, const void* g) {
    asm volatile("cp.async.cg.shared.global [%0], [%1], 16;"
                 :: "r"(saddr), "l"((size_t)__cvta_generic_to_global(g)) : "memory");
}
#define CP_COMMIT() asm volatile("cp.async.commit_group;" ::: "memory")
#define CP_WAIT0()  asm volatile("cp.async.wait_group 0;" ::: "memory")

__device__ __forceinline__ uint32_t pack_bf2(__nv_bfloat16 a, __nv_bfloat16 b) {
    __nv_bfloat162 t; t.x = a; t.y = b;
    return *reinterpret_cast<uint32_t*>(&t);
}
__device__ __forceinline__ void split2(float x, float y, uint32_t& hi, uint32_t& lo) {
    __nv_bfloat16 hx = __float2bfloat16(x);
    __nv_bfloat16 hy = __float2bfloat16(y);
    hi = pack_bf2(hx, hy);
    lo = pack_bf2(__float2bfloat16(x - __bfloat162float(hx)),
                  __float2bfloat16(y - __bfloat162float(hy)));
}

// ---------------------------------------------------------------------------
// Conversion kernels: fp32 -> bf16 hi/lo
// ---------------------------------------------------------------------------
__global__ __launch_bounds__(256) void convert_x_kernel(
    const float* __restrict__ q, const float* __restrict__ k,
    const float* __restrict__ v)
{
    const float* src = (blockIdx.y == 0) ? q : (blockIdx.y == 1) ? k : v;
    __nv_bfloat16* hi = g_Xhi + (size_t)blockIdx.y * MROWS * DMODEL;
    __nv_bfloat16* lo = g_Xlo + (size_t)blockIdx.y * MROWS * DMODEL;

    size_t i4 = (size_t)blockIdx.x * 256 + threadIdx.x;
    float4 x = ((const float4*)src)[i4];
    uint32_t h2[2], l2[2];
    split2(x.x, x.y, h2[0], l2[0]);
    split2(x.z, x.w, h2[1], l2[1]);
    ((uint32_t*)hi)[i4 * 2 + 0] = h2[0];
    ((uint32_t*)hi)[i4 * 2 + 1] = h2[1];
    ((uint32_t*)lo)[i4 * 2 + 0] = l2[0];
    ((uint32_t*)lo)[i4 * 2 + 1] = l2[1];
}

__global__ __launch_bounds__(256) void convert_wt_kernel(
    const float* __restrict__ Wq, const float* __restrict__ Wk,
    const float* __restrict__ Wv, const float* __restrict__ Wo)
{
    const float* W = (blockIdx.z == 0) ? Wq : (blockIdx.z == 1) ? Wk
                   : (blockIdx.z == 2) ? Wv : Wo;
    __nv_bfloat16* hi = g_Wthi + (size_t)blockIdx.z * DMODEL * DMODEL;
    __nv_bfloat16* lo = g_Wtlo + (size_t)blockIdx.z * DMODEL * DMODEL;

    __shared__ float t[32][33];
    int tx = threadIdx.x & 31, ty = threadIdx.x >> 5;    // 32 x 8
    int k0 = blockIdx.y * 32, n0 = blockIdx.x * 32;
#pragma unroll
    for (int d = 0; d < 4; d++)
        t[ty + 8 * d][tx] = W[(size_t)(k0 + ty + 8 * d) * DMODEL + n0 + tx];
    __syncthreads();
#pragma unroll
    for (int d = 0; d < 4; d++) {
        float val = t[tx][ty + 8 * d];
        __nv_bfloat16 h = __float2bfloat16(val);
        __nv_bfloat16 l = __float2bfloat16(val - __bfloat162float(h));
        size_t o = (size_t)(n0 + ty + 8 * d) * DMODEL + k0 + tx;
        hi[o] = h; lo[o] = l;
    }
}

// ---------------------------------------------------------------------------
// Split-bf16 HMMA GEMM. CTA 128x128, BK=32, 8 warps (2m x 4n).
// mode 0: fp32 out [M,DMODEL]; mode 1: bf16 hi/lo [B,H,S,d];
// mode 2: bf16 hi/lo transposed [B,H,d,S]
// ---------------------------------------------------------------------------
#define BM 128
#define BN 128
#define BK 32
#define AST 40

struct GemmPtrs {
    const __nv_bfloat16 *Ahi, *Alo, *Bhi, *Blo;
    const float* bias;
    float* out;
    __nv_bfloat16 *Ohi, *Olo;
};

__device__ __forceinline__ void gemm_body(const GemmPtrs& P, int m0, int n0,
                                          int mode)
{
    __shared__ __nv_bfloat16 sAh[BM * AST];
    __shared__ __nv_bfloat16 sAl[BM * AST];
    __shared__ __nv_bfloat16 sBh[BN * AST];
    __shared__ __nv_bfloat16 sBl[BN * AST];

    const int tid = threadIdx.x;
    const int wid = tid >> 5;
    const int lane = tid & 31;
    const int wm = (wid & 1) * 64;
    const int wn = (wid >> 1) * 32;

    const uint32_t uAh = smem_u32(sAh);
    const uint32_t uAl = smem_u32(sAl);
    const uint32_t uBh = smem_u32(sBh);
    const uint32_t uBl = smem_u32(sBl);

    float acc[4][4][4];
#pragma unroll
    for (int i = 0; i < 4; i++)
#pragma unroll
        for (int j = 0; j < 4; j++)
#pragma unroll
            for (int f = 0; f < 4; f++) acc[i][j][f] = 0.f;

    const int a_row = lane & 15;
    const int a_k8  = (lane >> 4) * 8;
    const int b_lr  = lane & 7;
    const int b_g   = lane >> 3;
    const int b_nadd = (b_g & 2) * 4;
    const int b_kadd = (b_g & 1) * 8;

    for (int kt = 0; kt < DMODEL; kt += BK) {
        for (int idx = tid; idx < 512; idx += 256) {
            int r = idx >> 2, c4 = idx & 3;
            int soff = r * AST + c4 * 8;
            size_t ga = (size_t)(m0 + r) * DMODEL + kt + c4 * 8;
            size_t gb = (size_t)(n0 + r) * DMODEL + kt + c4 * 8;
            cp16(uAh + soff * 2, P.Ahi + ga);
            cp16(uAl + soff * 2, P.Alo + ga);
            cp16(uBh + soff * 2, P.Bhi + gb);
            cp16(uBl + soff * 2, P.Blo + gb);
        }
        CP_COMMIT();
        CP_WAIT0();
        __syncthreads();

#pragma unroll
        for (int kk = 0; kk < BK; kk += 16) {
            uint32_t bh[2][4], bl[2][4];
#pragma unroll
            for (int p = 0; p < 2; p++) {
                uint32_t boff = ((wn + p * 16 + b_lr + b_nadd) * AST
                                 + kk + b_kadd) * 2;
                ldsm4(bh[p], uBh + boff);
                ldsm4(bl[p], uBl + boff);
            }
#pragma unroll
            for (int mt = 0; mt < 4; mt++) {
                uint32_t ah[4], al[4];
                uint32_t aoff = ((wm + mt * 16 + a_row) * AST + kk + a_k8) * 2;
                ldsm4(ah, uAh + aoff);
                ldsm4(al, uAl + aoff);
#pragma unroll
                for (int nt = 0; nt < 4; nt++) {
                    const uint32_t* fbh = &bh[nt >> 1][(nt & 1) * 2];
                    const uint32_t* fbl = &bl[nt >> 1][(nt & 1) * 2];
                    mma16816(acc[mt][nt], ah, fbh);
                    mma16816(acc[mt][nt], ah, fbl);
                    mma16816(acc[mt][nt], al, fbh);
                }
            }
        }
        __syncthreads();
    }

    const int rbase = m0 + wm + (lane >> 2);
    const int cbase = n0 + wn + (lane & 3) * 2;
#pragma unroll
    for (int mt = 0; mt < 4; mt++) {
#pragma unroll
        for (int nt = 0; nt < 4; nt++) {
            int n = cbase + nt * 8;
            float b0 = P.bias[n], b1 = P.bias[n + 1];
#pragma unroll
            for (int half = 0; half < 2; half++) {
                int r = rbase + mt * 16 + half * 8;
                float wx = acc[mt][nt][half * 2 + 0] + b0;
                float wy = acc[mt][nt][half * 2 + 1] + b1;
                if (mode == 0) {
                    float2 w2; w2.x = wx; w2.y = wy;
                    *(float2*)(P.out + (size_t)r * DMODEL + n) = w2;
                } else {
                    int b = r >> 11, ss = r & (SEQ - 1);
                    int h = n >> 6, dd = n & 63;
                    int bhh = b * NHEAD + h;
                    uint32_t hv, lv;
                    split2(wx, wy, hv, lv);
                    if (mode == 1) {
                        size_t o = ((size_t)bhh * SEQ + ss) * DHEAD + dd;
                        *(uint32_t*)(P.Ohi + o) = hv;
                        *(uint32_t*)(P.Olo + o) = lv;
                    } else {
                        __nv_bfloat162 h2 = *reinterpret_cast<__nv_bfloat162*>(&hv);
                        __nv_bfloat162 l2 = *reinterpret_cast<__nv_bfloat162*>(&lv);
                        size_t o0 = ((size_t)bhh * DHEAD + dd) * SEQ + ss;
                        size_t o1 = ((size_t)bhh * DHEAD + dd + 1) * SEQ + ss;
                        P.Ohi[o0] = h2.x; P.Ohi[o1] = h2.y;
                        P.Olo[o0] = l2.x; P.Olo[o1] = l2.y;
                    }
                }
            }
        }
    }
}

__global__ __launch_bounds__(256, 2) void gemm_qkv_kernel(
    const float* __restrict__ bq, const float* __restrict__ bk,
    const float* __restrict__ bv)
{
    int z = blockIdx.z;
    GemmPtrs P;
    P.Ahi = g_Xhi + (size_t)z * MROWS * DMODEL;
    P.Alo = g_Xlo + (size_t)z * MROWS * DMODEL;
    P.Bhi = g_Wthi + (size_t)z * DMODEL * DMODEL;
    P.Blo = g_Wtlo + (size_t)z * DMODEL * DMODEL;
    P.bias = (z == 0) ? bq : (z == 1) ? bk : bv;
    P.out = 0;
    P.Ohi = (z == 0) ? g_Qhi : (z == 1) ? g_Khi : g_Vthi;
    P.Olo = (z == 0) ? g_Qlo : (z == 1) ? g_Klo : g_Vtlo;
    gemm_body(P, blockIdx.y * BM, blockIdx.x * BN, (z == 2) ? 2 : 1);
}

__global__ __launch_bounds__(256, 2) void gemm_out_kernel(
    const float* __restrict__ bo, float* __restrict__ out)
{
    GemmPtrs P;
    P.Ahi = g_Chi; P.Alo = g_Clo;
    P.Bhi = g_Wthi + (size_t)3 * DMODEL * DMODEL;
    P.Blo = g_Wtlo + (size_t)3 * DMODEL * DMODEL;
    P.bias = bo; P.out = out; P.Ohi = 0; P.Olo = 0;
    gemm_body(P, blockIdx.y * BM, blockIdx.x * BN, 0);
}

// ---------------------------------------------------------------------------
// Tensor-core flash attention, KT=32 keys/tile, cp.async double-buffered,
// 2 CTAs/SM. Block: 128 q-rows x one (b,h), 8 warps x 16 rows.
// smem layout (halves), per buffer (9728): Kh[32x72] Kl[32x72] Vh[64x40] Vl[64x40]
// ---------------------------------------------------------------------------
#define KST 72
#define VST 40
#define BUFH 9728   // halves per buffer

__global__ __launch_bounds__(256, 2) void attn_kernel(const int* __restrict__ mask)
{
    __shared__ __nv_bfloat16 sm[2 * BUFH];   // 38,912 B
    __shared__ float sMask[2][32];

    const int bh = blockIdx.y;
    const int b = bh >> 4;
    const int h = bh & 15;
    const int q0 = blockIdx.x * 128;
    const int tid = threadIdx.x;
    const int wid = tid >> 5;
    const int lane = tid & 31;
    const int wm = wid * 16;

    const __nv_bfloat16* Qhi = g_Qhi + ((size_t)bh * SEQ + q0) * DHEAD;
    const __nv_bfloat16* Qlo = g_Qlo + ((size_t)bh * SEQ + q0) * DHEAD;
    const __nv_bfloat16* Khi = g_Khi + (size_t)bh * SEQ * DHEAD;
    const __nv_bfloat16* Klo = g_Klo + (size_t)bh * SEQ * DHEAD;
    const __nv_bfloat16* Vth = g_Vthi + (size_t)bh * DHEAD * SEQ;
    const __nv_bfloat16* Vtl = g_Vtlo + (size_t)bh * DHEAD * SEQ;
    const int* mrow = mask + b * SEQ;

    const uint32_t uS = smem_u32(sm);

    const int a_row = lane & 15;
    const int a_k8  = (lane >> 4) * 8;
    const int b_lr  = lane & 7;
    const int b_g   = lane >> 3;
    const int b_nadd = (b_g & 2) * 4;
    const int b_kadd = (b_g & 1) * 8;

    // ---- stage Q (128x64 hi/lo) into smem union, load fragments
    for (int idx = tid; idx < 1024; idx += 256) {
        int r = idx >> 3, c8 = idx & 7;
        int soff = r * KST + c8 * 8;
        size_t g = (size_t)r * DHEAD + c8 * 8;
        *(uint4*)&sm[soff]              = *(const uint4*)(Qhi + g);
        *(uint4*)&sm[128 * KST + soff]  = *(const uint4*)(Qlo + g);
    }
    __syncthreads();

    uint32_t qh[4][4], ql[4][4];
#pragma unroll
    for (int kc = 0; kc < 4; kc++) {
        uint32_t aoff = ((wm + a_row) * KST + kc * 16 + a_k8) * 2;
        ldsm4(qh[kc], uS + aoff);
        ldsm4(ql[kc], uS + (128 * KST) * 2 + aoff);
    }
    __syncthreads();

    // per-thread cp.async slots
    const int k_r = tid >> 3, k_c8 = tid & 7;      // K: 32 rows x 8 chunks
    const int v_r = tid >> 2, v_c8 = tid & 3;      // V: 64 rows x 4 chunks

    float O[8][4];
#pragma unroll
    for (int i = 0; i < 8; i++)
#pragma unroll
        for (int j = 0; j < 4; j++) O[i][j] = 0.f;
    float m_i[2] = {-1e30f, -1e30f};
    float l_i[2] = {0.f, 0.f};

    // prefetch tile 0 into buffer 0
    {
        uint32_t base = uS;
        size_t gk = (size_t)k_r * DHEAD + k_c8 * 8;
        cp16(base + (k_r * KST + k_c8 * 8) * 2, Khi + gk);
        cp16(base + (2304 + k_r * KST + k_c8 * 8) * 2, Klo + gk);
        size_t gv = (size_t)v_r * SEQ + v_c8 * 8;
        cp16(base + (4608 + v_r * VST + v_c8 * 8) * 2, Vth + gv);
        cp16(base + (7168 + v_r * VST + v_c8 * 8) * 2, Vtl + gv);
        CP_COMMIT();
        if (tid < 32) sMask[0][tid] = (float)mrow[tid] * (-1000000000.0f);
    }
    CP_WAIT0();
    __syncthreads();

    int buf = 0;
    for (int kt = 0; kt < SEQ; kt += 32) {
        // issue next tile into other buffer
        if (kt + 32 < SEQ) {
            uint32_t base = uS + (buf ^ 1) * BUFH * 2;
            size_t gk = (size_t)(kt + 32 + k_r) * DHEAD + k_c8 * 8;
            cp16(base + (k_r * KST + k_c8 * 8) * 2, Khi + gk);
            cp16(base + (2304 + k_r * KST + k_c8 * 8) * 2, Klo + gk);
            size_t gv = (size_t)v_r * SEQ + kt + 32 + v_c8 * 8;
            cp16(base + (4608 + v_r * VST + v_c8 * 8) * 2, Vth + gv);
            cp16(base + (7168 + v_r * VST + v_c8 * 8) * 2, Vtl + gv);
            CP_COMMIT();
            if (tid < 32)
                sMask[buf ^ 1][tid] = (float)mrow[kt + 32 + tid] * (-1000000000.0f);
        }

        const uint32_t uKh = uS + buf * BUFH * 2;
        const uint32_t uKl = uKh + 2304 * 2;
        const uint32_t uVh = uS + (buf * BUFH + 4608) * 2;
        const uint32_t uVl = uVh + 2560 * 2;

        // ---- S = Q K^T (16 x 32 per warp), split 3-product
        float s[4][4];
#pragma unroll
        for (int i = 0; i < 4; i++)
#pragma unroll
            for (int j = 0; j < 4; j++) s[i][j] = 0.f;

#pragma unroll
        for (int kc = 0; kc < 4; kc++) {
            uint32_t kbh[2][4], kbl[2][4];
#pragma unroll
            for (int p = 0; p < 2; p++) {
                uint32_t boff = ((p * 16 + b_lr + b_nadd) * KST
                                 + kc * 16 + b_kadd) * 2;
                ldsm4(kbh[p], uKh + boff);
                ldsm4(kbl[p], uKl + boff);
            }
#pragma unroll
            for (int nt = 0; nt < 4; nt++) {
                const uint32_t* fbh = &kbh[nt >> 1][(nt & 1) * 2];
                const uint32_t* fbl = &kbl[nt >> 1][(nt & 1) * 2];
                mma16816(s[nt], qh[kc], fbh);
                mma16816(s[nt], qh[kc], fbl);
                mma16816(s[nt], ql[kc], fbh);
            }
        }

        // ---- scale + mask
        const int c0 = (lane & 3) * 2;
#pragma unroll
        for (int nt = 0; nt < 4; nt++) {
            float bias0 = sMask[buf][nt * 8 + c0];
            float bias1 = sMask[buf][nt * 8 + c0 + 1];
            s[nt][0] = s[nt][0] * 0.125f + bias0;
            s[nt][1] = s[nt][1] * 0.125f + bias1;
            s[nt][2] = s[nt][2] * 0.125f + bias0;
            s[nt][3] = s[nt][3] * 0.125f + bias1;
        }

        // ---- online softmax (rows r0=lane>>2, r1=r0+8)
        float mx0 = -1e30f, mx1 = -1e30f;
#pragma unroll
        for (int nt = 0; nt < 4; nt++) {
            mx0 = fmaxf(mx0, fmaxf(s[nt][0], s[nt][1]));
            mx1 = fmaxf(mx1, fmaxf(s[nt][2], s[nt][3]));
        }
        mx0 = fmaxf(mx0, __shfl_xor_sync(0xffffffffu, mx0, 1));
        mx0 = fmaxf(mx0, __shfl_xor_sync(0xffffffffu, mx0, 2));
        mx1 = fmaxf(mx1, __shfl_xor_sync(0xffffffffu, mx1, 1));
        mx1 = fmaxf(mx1, __shfl_xor_sync(0xffffffffu, mx1, 2));
        float mnew0 = fmaxf(m_i[0], mx0);
        float mnew1 = fmaxf(m_i[1], mx1);

        float rs0 = 0.f, rs1 = 0.f;
#pragma unroll
        for (int nt = 0; nt < 4; nt++) {
            s[nt][0] = __expf(s[nt][0] - mnew0);
            s[nt][1] = __expf(s[nt][1] - mnew0);
            s[nt][2] = __expf(s[nt][2] - mnew1);
            s[nt][3] = __expf(s[nt][3] - mnew1);
            rs0 += s[nt][0] + s[nt][1];
            rs1 += s[nt][2] + s[nt][3];
        }
        rs0 += __shfl_xor_sync(0xffffffffu, rs0, 1);
        rs0 += __shfl_xor_sync(0xffffffffu, rs0, 2);
        rs1 += __shfl_xor_sync(0xffffffffu, rs1, 1);
        rs1 += __shfl_xor_sync(0xffffffffu, rs1, 2);

        float alpha0 = __expf(m_i[0] - mnew0);
        float alpha1 = __expf(m_i[1] - mnew1);
        l_i[0] = l_i[0] * alpha0 + rs0;
        l_i[1] = l_i[1] * alpha1 + rs1;
        m_i[0] = mnew0; m_i[1] = mnew1;
#pragma unroll
        for (int nt = 0; nt < 8; nt++) {
            O[nt][0] *= alpha0; O[nt][1] *= alpha0;
            O[nt][2] *= alpha1; O[nt][3] *= alpha1;
        }

        // ---- P fragments (registers only)
        uint32_t ph[2][4], pl[2][4];
#pragma unroll
        for (int kc = 0; kc < 2; kc++) {
            int n0t = 2 * kc, n1t = 2 * kc + 1;
            split2(s[n0t][0], s[n0t][1], ph[kc][0], pl[kc][0]);
            split2(s[n0t][2], s[n0t][3], ph[kc][1], pl[kc][1]);
            split2(s[n1t][0], s[n1t][1], ph[kc][2], pl[kc][2]);
            split2(s[n1t][2], s[n1t][3], ph[kc][3], pl[kc][3]);
        }

        // ---- O += P V (contraction over 32 keys)
#pragma unroll
        for (int kc = 0; kc < 2; kc++) {
            uint32_t vbh[4][4], vbl[4][4];
#pragma unroll
            for (int p = 0; p < 4; p++) {
                uint32_t boff = ((p * 16 + b_lr + b_nadd) * VST
                                 + kc * 16 + b_kadd) * 2;
                ldsm4(vbh[p], uVh + boff);
                ldsm4(vbl[p], uVl + boff);
            }
#pragma unroll
            for (int nt = 0; nt < 8; nt++) {
                const uint32_t* fbh = &vbh[nt >> 1][(nt & 1) * 2];
                const uint32_t* fbl = &vbl[nt >> 1][(nt & 1) * 2];
                mma16816(O[nt], ph[kc], fbh);
                mma16816(O[nt], ph[kc], fbl);
                mma16816(O[nt], pl[kc], fbh);
            }
        }

        CP_WAIT0();
        __syncthreads();
        buf ^= 1;
    }

    // ---- finalize and write ctx hi/lo in [B,S,D] layout
    float inv0 = 1.0f / l_i[0];
    float inv1 = 1.0f / l_i[1];
    int r0g = q0 + wm + (lane >> 2);
    int r1g = r0g + 8;
#pragma unroll
    for (int nt = 0; nt < 8; nt++) {
        int col = h * DHEAD + nt * 8 + (lane & 3) * 2;
        uint32_t hv, lv;
        split2(O[nt][0] * inv0, O[nt][1] * inv0, hv, lv);
        size_t o0 = ((size_t)b * SEQ + r0g) * DMODEL + col;
        *(uint32_t*)(g_Chi + o0) = hv;
        *(uint32_t*)(g_Clo + o0) = lv;
        split2(O[nt][2] * inv1, O[nt][3] * inv1, hv, lv);
        size_t o1 = ((size_t)b * SEQ + r1g) * DMODEL + col;
        *(uint32_t*)(g_Chi + o1) = hv;
        *(uint32_t*)(g_Clo + o1) = lv;
    }
}

// ---------------------------------------------------------------------------
// Launch: pure kernel launches only
// ---------------------------------------------------------------------------
extern "C" void kernel_launch(void* const* d_in, const int* in_sizes, int n_in,
                              void* d_out, int out_size)
{
    const float* v  = (const float*)d_in[0];
    const float* k  = (const float*)d_in[1];
    const float* q  = (const float*)d_in[2];
    const int*   mask = (const int*)d_in[3];
    const float* Wq = (const float*)d_in[4];
    const float* bq = (const float*)d_in[5];
    const float* Wk = (const float*)d_in[6];
    const float* bk = (const float*)d_in[7];
    const float* Wv = (const float*)d_in[8];
    const float* bv = (const float*)d_in[9];
    const float* Wo = (const float*)d_in[10];
    const float* bo = (const float*)d_in[11];
    float* out = (float*)d_out;

    convert_x_kernel<<<dim3(MROWS * DMODEL / 4 / 256, 3), 256>>>(q, k, v);
    convert_wt_kernel<<<dim3(32, 32, 4), 256>>>(Wq, Wk, Wv, Wo);

    gemm_qkv_kernel<<<dim3(DMODEL / BN, MROWS / BM, 3), 256>>>(bq, bk, bv);

    attn_kernel<<<dim3(SEQ / 128, BB * NHEAD), 256>>>(mask);

    gemm_out_kernel<<<dim3(DMODEL / BN, MROWS / BM), 256>>>(bo, out);
}